// round 15
// baseline (speedup 1.0000x reference)
#include <cuda_runtime.h>
#include <cuda_fp16.h>
#include <cstdint>

// Problem constants
#define BB 16
#define SS 4096
#define EE 1024
#define HH 512
#define NROWS (BB*SS)          // 65536
#define NSPLIT 8               // H split (BN=64)
#define CSPLIT 32              // s-split for context pass

// GEMM tiling: BM=128 x BN=64, 128 threads (4 warps, warp tile 64x32)
#define BM 128
#define BN 64
#define BK 64                  // fp16 elems = 128B rows (SW128 atom)
#define KITERS (EE/BK)         // 16
#define STAGES 2
#define A_BYTES (BM*BK*2)      // 16384
#define B_BYTES (BN*BK*2)      // 8192
#define STAGE_BYTES (A_BYTES + B_BYTES)  // 24576

// Persistent fused-GEMM scheduling
#define NCTA 592               // 148 SMs x 4 CTAs (guaranteed-resident)
#define NTILE (NROWS/BM)       // 512 m-tiles
#define LOOK (NCTA/8)          // 74: one item-wave of tiles

// Scratch (__device__ globals; allocation-free rule), 16B+ aligned.
__device__ __align__(128) __half g_encH[(size_t)NROWS*EE];   // fp16 encoder copy
__device__ __align__(128) __half g_WeTh[HH*EE];              // We^T fp16, K-major
__device__ __align__(128) float  g_comb[BB*HH];              // dec_proj + bd + be
__device__ __align__(128) float  g_partial[NSPLIT*NROWS];    // partial scores
__device__ __align__(128) float  g_attn[NROWS];              // softmax weights
__device__ __align__(128) float  g_ctx_part[CSPLIT*BB*EE];   // context partials
__device__ int g_tile_cnt[NTILE];                             // conversion counters

__device__ __forceinline__ uint32_t smem_u32(const void* p) {
    uint32_t a;
    asm("{ .reg .u64 t; cvta.to.shared.u64 t, %1; cvt.u32.u64 %0, t; }" : "=r"(a) : "l"(p));
    return a;
}
__device__ __forceinline__ void cp16(uint32_t dst, const void* src) {
    asm volatile("cp.async.cg.shared.global [%0], [%1], 16;" :: "r"(dst), "l"(src) : "memory");
}
__device__ __forceinline__ void ldmatrix_x4(uint32_t r[4], uint32_t addr) {
    asm volatile("ldmatrix.sync.aligned.m8n8.x4.shared.b16 {%0,%1,%2,%3}, [%4];"
                 : "=r"(r[0]), "=r"(r[1]), "=r"(r[2]), "=r"(r[3]) : "r"(addr));
}
__device__ __forceinline__ void mma_f16(float d[4], const uint32_t a[4], const uint32_t b[2]) {
    asm volatile(
        "mma.sync.aligned.m16n8k16.row.col.f32.f16.f16.f32 "
        "{%0,%1,%2,%3}, {%4,%5,%6,%7}, {%8,%9}, {%0,%1,%2,%3};"
        : "+f"(d[0]), "+f"(d[1]), "+f"(d[2]), "+f"(d[3])
        : "r"(a[0]), "r"(a[1]), "r"(a[2]), "r"(a[3]), "r"(b[0]), "r"(b[1]));
}

// Convert 16 rows (tile, slice) of encoder fp32 -> fp16 into g_encH.
__device__ __forceinline__ void convert_slice(const float4* __restrict__ in4,
                                              int tile, int slice, int tid) {
    const size_t rb = (size_t)tile*BM + slice*16;        // first row
    const float4* src = in4 + rb*256;                    // 256 float4 / row
    uint4* dst = reinterpret_cast<uint4*>(g_encH) + rb*128;  // 128 uint4 / row
    #pragma unroll
    for (int bt = 0; bt < 4; bt++) {
        const int ii = bt*128 + tid;
        float4 v[8];
        #pragma unroll
        for (int j = 0; j < 8; j++) v[j] = src[(size_t)ii*8 + j];
        #pragma unroll
        for (int j = 0; j < 4; j++) {
            __half2 h0 = __floats2half2_rn(v[2*j].x,   v[2*j].y);
            __half2 h1 = __floats2half2_rn(v[2*j].z,   v[2*j].w);
            __half2 h2 = __floats2half2_rn(v[2*j+1].x, v[2*j+1].y);
            __half2 h3 = __floats2half2_rn(v[2*j+1].z, v[2*j+1].w);
            uint4 o;
            o.x = *reinterpret_cast<uint32_t*>(&h0);
            o.y = *reinterpret_cast<uint32_t*>(&h1);
            o.z = *reinterpret_cast<uint32_t*>(&h2);
            o.w = *reinterpret_cast<uint32_t*>(&h3);
            dst[(size_t)ii*4 + j] = o;
        }
    }
}

__device__ __forceinline__ void tile_arrive(int t, int tid) {
    __threadfence();
    __syncthreads();
    if (tid == 0) {
        __threadfence();
        atomicAdd(&g_tile_cnt[t], 1);
    }
}

__device__ __forceinline__ void tile_wait(int t, int tid) {
    if (tid == 0) {
        int v;
        for (;;) {
            asm volatile("ld.acquire.gpu.global.s32 %0, [%1];"
                         : "=r"(v) : "l"(g_tile_cnt + t) : "memory");
            if (v >= 8) break;
            __nanosleep(64);
        }
    }
    __syncthreads();
}

// ---------------------------------------------------------------------------
// Reset conversion counters (runs every launch/replay, before the fused GEMM).
// ---------------------------------------------------------------------------
__global__ __launch_bounds__(256) void reset_cnt_kernel() {
    const int i = blockIdx.x*256 + threadIdx.x;
    if (i < NTILE) g_tile_cnt[i] = 0;
}

// ---------------------------------------------------------------------------
// We [1024,512] -> g_WeTh [512,1024] fp16 (transposed, K-major).
// ---------------------------------------------------------------------------
__global__ __launch_bounds__(256) void convert_we_kernel(const float* __restrict__ We) {
    __shared__ float t[32][33];
    const int bx = blockIdx.x;  // K block (32)
    const int by = blockIdx.y;  // N block (16)
    const int x = threadIdx.x & 31;
    const int y = threadIdx.x >> 5;
    #pragma unroll
    for (int i = 0; i < 32; i += 8)
        t[y + i][x] = We[(bx*32 + y + i)*HH + by*32 + x];
    __syncthreads();
    #pragma unroll
    for (int i = 0; i < 32; i += 8)
        g_WeTh[(by*32 + y + i)*EE + bx*32 + x] = __float2half_rn(t[x][y + i]);
}

// ---------------------------------------------------------------------------
// dec_proj: comb[b,h] = dec[b,:] @ Wd[:,h] + bd[h] + be[h].
// Grid (16, 8): 64 h-lanes x 4 K-quarters; smem combine.
// ---------------------------------------------------------------------------
__global__ __launch_bounds__(256) void dec_proj_kernel(
    const float* __restrict__ dec, const float* __restrict__ Wd,
    const float* __restrict__ be, const float* __restrict__ bd) {
    __shared__ float sd[EE];
    __shared__ float part[4][64];
    const int b = blockIdx.x;
    const int hl = threadIdx.x & 63;
    const int q  = threadIdx.x >> 6;          // 0..3
    const int h  = blockIdx.y * 64 + hl;
    for (int i = threadIdx.x; i < EE; i += 256) sd[i] = dec[b*EE + i];
    __syncthreads();
    const float* wp = Wd + (size_t)(q*256)*HH + h;
    const float* dp = sd + q*256;
    float a0 = 0.f, a1 = 0.f, a2 = 0.f, a3 = 0.f;
    #pragma unroll 4
    for (int k = 0; k < 256; k += 4) {
        a0 += dp[k  ] * wp[(size_t)(k  )*HH];
        a1 += dp[k+1] * wp[(size_t)(k+1)*HH];
        a2 += dp[k+2] * wp[(size_t)(k+2)*HH];
        a3 += dp[k+3] * wp[(size_t)(k+3)*HH];
    }
    part[q][hl] = (a0 + a1) + (a2 + a3);
    __syncthreads();
    if (q == 0)
        g_comb[b*HH + h] = (part[0][hl] + part[1][hl]) + (part[2][hl] + part[3][hl])
                         + bd[h] + be[h];
}

// ---------------------------------------------------------------------------
// PERSISTENT fused convert+GEMM. Grid = 592 CTAs (all resident at 4/SM).
// CTA c: n-split n = c&7 (fixed), tiles m = (c>>3) + 74k.
// Pre-phase: convert tile (c>>3), slice n. Each item: convert slice n of
// tile m+74 (lookahead), then spin on tile m's counter (8 arrivals) and run
// the R14 2-stage mma mainloop + tanh score epilogue.
// ---------------------------------------------------------------------------
__global__ __launch_bounds__(128, 4) void gemm_fused(
    const float4* __restrict__ enc4, const float* __restrict__ Wo) {
    extern __shared__ char dsmem_raw[];
    __shared__ float red[2][BM];
    __shared__ float sm_comb[BN], sm_wo[BN];

    const int tid = threadIdx.x;
    const int c   = blockIdx.x;
    const int n   = c & 7;
    const int n0  = n * BN;
    const int cg  = c >> 3;            // 0..73

    const uint32_t smem_base = (smem_u32(dsmem_raw) + 127u) & ~127u;

    if (tid < BN) sm_wo[tid] = Wo[n0 + tid];

    const int warp = tid >> 5;
    const int lane = tid & 31;
    const int wm = warp >> 1;
    const int wn = warp & 1;
    const int g  = lane >> 2;
    const int tig = lane & 3;

    const __half* gB = g_WeTh + (size_t)n0 * EE;

    const int lrow = tid >> 3;          // 0..15
    const int lcb  = (tid & 7) * 16;
    const uint32_t st_sw = (uint32_t)(lrow*128 + lcb) ^ ((lrow & 7) << 4);

    uint32_t a_raw[4], a_xor[4];
    #pragma unroll
    for (int mb = 0; mb < 4; mb++) {
        int row = wm*64 + mb*16 + (lane & 15);
        a_raw[mb] = row*128 + ((lane >> 4) * 16);
        a_xor[mb] = (row & 7) << 4;
    }
    uint32_t b_raw[2], b_xor[2];
    #pragma unroll
    for (int p = 0; p < 2; p++) {
        int row = wn*32 + p*16 + ((lane & 16) ? 8 : 0) + (lane & 7);
        b_raw[p] = row*128 + (((lane >> 3) & 1) * 16);
        b_xor[p] = (row & 7) << 4;
    }

    // Pre-phase: convert tile cg (slice n) so tiles [0,74) are ready.
    convert_slice(enc4, cg, n, tid);
    tile_arrive(cg, tid);

    for (int k = 0; ; k++) {
        const int m = cg + LOOK*k;
        if (m >= NTILE) break;

        // Lookahead conversion for the next item-wave's tile.
        const int mt = m + LOOK;
        if (mt < NTILE) {
            convert_slice(enc4, mt, n, tid);
            tile_arrive(mt, tid);
        }

        // Wait for tile m's 8 conversion slices.
        tile_wait(m, tid);

        const int r0 = m * BM;
        const int b  = r0 >> 12;
        if (tid < BN) sm_comb[tid] = g_comb[b*HH + n0 + tid];
        const __half* gA = g_encH + (size_t)r0 * EE;

        float acc[4][4][4];
        #pragma unroll
        for (int mb = 0; mb < 4; mb++)
            #pragma unroll
            for (int nb = 0; nb < 4; nb++)
                #pragma unroll
                for (int e = 0; e < 4; e++) acc[mb][nb][e] = 0.f;

        // prologue: fill stages 0,1
        #pragma unroll
        for (int p = 0; p < STAGES; p++) {
            uint32_t stA = smem_base + p*STAGE_BYTES;
            uint32_t stB = stA + A_BYTES;
            const int k0 = p * BK;
            #pragma unroll
            for (int u = 0; u < 8; u++)
                cp16(stA + st_sw + u*2048, (const char*)(gA + (size_t)(lrow + u*16)*EE + k0) + lcb);
            #pragma unroll
            for (int u = 0; u < 4; u++)
                cp16(stB + st_sw + u*2048, (const char*)(gB + (size_t)(lrow + u*16)*EE + k0) + lcb);
            asm volatile("cp.async.commit_group;" ::: "memory");
        }

        for (int i = 0; i < KITERS; i++) {
            asm volatile("cp.async.wait_group 1;" ::: "memory");
            __syncthreads();

            const uint32_t stA = smem_base + (i & 1)*STAGE_BYTES;
            const uint32_t stB = stA + A_BYTES;

            #pragma unroll
            for (int ks = 0; ks < 4; ks++) {
                uint32_t afr[4][4], bfr[4][2];
                #pragma unroll
                for (int mb = 0; mb < 4; mb++)
                    ldmatrix_x4(afr[mb], stA + ((a_raw[mb] + ks*32) ^ a_xor[mb]));
                #pragma unroll
                for (int p = 0; p < 2; p++) {
                    uint32_t r[4];
                    ldmatrix_x4(r, stB + ((b_raw[p] + ks*32) ^ b_xor[p]));
                    bfr[2*p][0]   = r[0]; bfr[2*p][1]   = r[1];
                    bfr[2*p+1][0] = r[2]; bfr[2*p+1][1] = r[3];
                }
                #pragma unroll
                for (int mb = 0; mb < 4; mb++)
                    #pragma unroll
                    for (int nb = 0; nb < 4; nb++)
                        mma_f16(acc[mb][nb], afr[mb], bfr[nb]);
            }

            __syncthreads();
            if (i + 2 < KITERS) {
                uint32_t nA = smem_base + (i & 1)*STAGE_BYTES;
                uint32_t nB = nA + A_BYTES;
                const int k0 = (i + 2) * BK;
                #pragma unroll
                for (int u = 0; u < 8; u++)
                    cp16(nA + st_sw + u*2048, (const char*)(gA + (size_t)(lrow + u*16)*EE + k0) + lcb);
                #pragma unroll
                for (int u = 0; u < 4; u++)
                    cp16(nB + st_sw + u*2048, (const char*)(gB + (size_t)(lrow + u*16)*EE + k0) + lcb);
            }
            asm volatile("cp.async.commit_group;" ::: "memory");
        }
        asm volatile("cp.async.wait_group 0;" ::: "memory");

        // Epilogue: score = sum_n tanh(acc + comb[n]) * wo[n]
        float rs[4][2];
        #pragma unroll
        for (int mb = 0; mb < 4; mb++) { rs[mb][0] = 0.f; rs[mb][1] = 0.f; }
        #pragma unroll
        for (int mb = 0; mb < 4; mb++) {
            #pragma unroll
            for (int nb = 0; nb < 4; nb++) {
                int col = wn*32 + nb*8 + tig*2;
                float c0 = sm_comb[col], c1 = sm_comb[col+1];
                float w0 = sm_wo[col],   w1 = sm_wo[col+1];
                float t0, t1, t2, t3;
                asm("tanh.approx.f32 %0, %1;" : "=f"(t0) : "f"(acc[mb][nb][0] + c0));
                asm("tanh.approx.f32 %0, %1;" : "=f"(t1) : "f"(acc[mb][nb][1] + c1));
                asm("tanh.approx.f32 %0, %1;" : "=f"(t2) : "f"(acc[mb][nb][2] + c0));
                asm("tanh.approx.f32 %0, %1;" : "=f"(t3) : "f"(acc[mb][nb][3] + c1));
                rs[mb][0] += t0*w0 + t1*w1;
                rs[mb][1] += t2*w0 + t3*w1;
            }
        }
        __syncthreads();   // red[] safe to overwrite (prev item fully drained)
        #pragma unroll
        for (int mb = 0; mb < 4; mb++)
            #pragma unroll
            for (int hh = 0; hh < 2; hh++) {
                float v = rs[mb][hh];
                v += __shfl_xor_sync(0xffffffffu, v, 1);
                v += __shfl_xor_sync(0xffffffffu, v, 2);
                if (tig == 0) red[wn][wm*64 + mb*16 + hh*8 + g] = v;
            }
        __syncthreads();
        if (tid < BM)
            g_partial[n * NROWS + r0 + tid] = red[0][tid] + red[1][tid];
        __syncthreads();   // all reads of red/sm_comb done before next item
    }
}

// ---------------------------------------------------------------------------
// softmax over S per batch (sums 8 N-chunk partials)
// ---------------------------------------------------------------------------
__global__ __launch_bounds__(1024) void softmax_kernel() {
    const int b = blockIdx.x;
    const int tid = threadIdx.x;
    __shared__ float sred[32];
    __shared__ float sbcast;

    float sc[4];
    float m = -1e30f;
    #pragma unroll
    for (int i = 0; i < 4; i++) {
        int s = b*SS + tid + i*1024;
        float v = 0.f;
        #pragma unroll
        for (int p = 0; p < NSPLIT; p++) v += g_partial[p*NROWS + s];
        sc[i] = v;
        m = fmaxf(m, v);
    }
    #pragma unroll
    for (int o = 16; o; o >>= 1) m = fmaxf(m, __shfl_xor_sync(0xffffffffu, m, o));
    if ((tid & 31) == 0) sred[tid >> 5] = m;
    __syncthreads();
    if (tid < 32) {
        float v = sred[tid];
        #pragma unroll
        for (int o = 16; o; o >>= 1) v = fmaxf(v, __shfl_xor_sync(0xffffffffu, v, o));
        if (tid == 0) sbcast = v;
    }
    __syncthreads();
    const float bm = sbcast;

    float sum = 0.f;
    #pragma unroll
    for (int i = 0; i < 4; i++) { sc[i] = __expf(sc[i] - bm); sum += sc[i]; }
    #pragma unroll
    for (int o = 16; o; o >>= 1) sum += __shfl_xor_sync(0xffffffffu, sum, o);
    __syncthreads();
    if ((tid & 31) == 0) sred[tid >> 5] = sum;
    __syncthreads();
    if (tid < 32) {
        float v = sred[tid];
        #pragma unroll
        for (int o = 16; o; o >>= 1) v += __shfl_xor_sync(0xffffffffu, v, o);
        if (tid == 0) sbcast = v;
    }
    __syncthreads();
    const float inv = 1.0f / sbcast;
    #pragma unroll
    for (int i = 0; i < 4; i++) g_attn[b*SS + tid + i*1024] = sc[i] * inv;
}

// ---------------------------------------------------------------------------
// Context partials from fp16 encoder copy. Grid (16, 32), block 256.
// ---------------------------------------------------------------------------
__global__ __launch_bounds__(256) void ctx_partial_kernel() {
    __shared__ float sa[128];
    __shared__ float part[128][8];
    const int b = blockIdx.x, sp = blockIdx.y;
    const int tid = threadIdx.x;
    const int half = tid >> 7;
    const int c = tid & 127;
    if (tid < 128) sa[tid] = g_attn[b*SS + sp*128 + tid];
    __syncthreads();

    const __half* ep = g_encH + ((size_t)(b*SS + sp*128 + half)) * EE + c*8;
    float a[8] = {0,0,0,0,0,0,0,0};
    #pragma unroll 8
    for (int s = 0; s < 128; s += 2) {
        uint4 v = *reinterpret_cast<const uint4*>(ep + (size_t)s*EE);
        float w = sa[s + half];
        __half2 h0 = *reinterpret_cast<__half2*>(&v.x);
        __half2 h1 = *reinterpret_cast<__half2*>(&v.y);
        __half2 h2 = *reinterpret_cast<__half2*>(&v.z);
        __half2 h3 = *reinterpret_cast<__half2*>(&v.w);
        float2 f0 = __half22float2(h0), f1 = __half22float2(h1);
        float2 f2 = __half22float2(h2), f3 = __half22float2(h3);
        a[0] += w*f0.x; a[1] += w*f0.y; a[2] += w*f1.x; a[3] += w*f1.y;
        a[4] += w*f2.x; a[5] += w*f2.y; a[6] += w*f3.x; a[7] += w*f3.y;
    }
    if (half == 1) {
        #pragma unroll
        for (int j = 0; j < 8; j++) part[c][j] = a[j];
    }
    __syncthreads();
    if (half == 0) {
        float4 o0, o1;
        o0.x = a[0] + part[c][0]; o0.y = a[1] + part[c][1];
        o0.z = a[2] + part[c][2]; o0.w = a[3] + part[c][3];
        o1.x = a[4] + part[c][4]; o1.y = a[5] + part[c][5];
        o1.z = a[6] + part[c][6]; o1.w = a[7] + part[c][7];
        float* dst = &g_ctx_part[(size_t)(sp*BB + b)*EE + c*8];
        *reinterpret_cast<float4*>(dst)     = o0;
        *reinterpret_cast<float4*>(dst + 4) = o1;
    }
}

// ---------------------------------------------------------------------------
// Final reduce of context partials.
// ---------------------------------------------------------------------------
__global__ __launch_bounds__(256) void ctx_reduce_kernel(float* __restrict__ out) {
    const int i = blockIdx.x * 256 + threadIdx.x;  // 16384 outputs
    float acc = 0.f;
    #pragma unroll
    for (int s = 0; s < CSPLIT; s++) acc += g_ctx_part[(size_t)s*BB*EE + i];
    out[i] = acc;
}

// ---------------------------------------------------------------------------
extern "C" void kernel_launch(void* const* d_in, const int* in_sizes, int n_in,
                              void* d_out, int out_size) {
    const float* enc = (const float*)d_in[0];  // [16,4096,1024]
    const float* dec = (const float*)d_in[1];  // [16,1024]
    const float* We  = (const float*)d_in[2];  // [1024,512]
    const float* be  = (const float*)d_in[3];  // [512]
    const float* Wd  = (const float*)d_in[4];  // [1024,512]
    const float* bd  = (const float*)d_in[5];  // [512]
    const float* Wo  = (const float*)d_in[6];  // [512,1]
    // d_in[7] = bo: softmax shift-invariant -> unused.

    // One-time side stream + events (resource init; captured graph identical
    // on every capture).
    static cudaStream_t s2 = nullptr;
    static cudaEvent_t ev_fork = nullptr, ev_join = nullptr;
    if (s2 == nullptr) {
        cudaStreamCreateWithFlags(&s2, cudaStreamNonBlocking);
        cudaEventCreateWithFlags(&ev_fork, cudaEventDisableTiming);
        cudaEventCreateWithFlags(&ev_join, cudaEventDisableTiming);
    }

    const int dyn_smem = STAGES*STAGE_BYTES + 256;  // 49408
    cudaFuncSetAttribute(gemm_fused,
                         cudaFuncAttributeMaxDynamicSharedMemorySize, dyn_smem);

    // Fork: weight-side kernels on s2 (overlap the counter reset + launch).
    cudaEventRecord(ev_fork, 0);
    cudaStreamWaitEvent(s2, ev_fork, 0);
    convert_we_kernel<<<dim3(EE/32, HH/32), 256, 0, s2>>>(We);
    dec_proj_kernel<<<dim3(BB, HH/64), 256, 0, s2>>>(dec, Wd, be, bd);
    cudaEventRecord(ev_join, s2);

    // Main chain.
    reset_cnt_kernel<<<2, 256>>>();
    cudaStreamWaitEvent(0, ev_join, 0);
    gemm_fused<<<NCTA, 128, dyn_smem>>>((const float4*)enc, Wo);
    softmax_kernel<<<BB, 1024>>>();
    ctx_partial_kernel<<<dim3(BB, CSPLIT), 256>>>();
    ctx_reduce_kernel<<<BB*EE/256, 256>>>((float*)d_out);
}

// round 16
// speedup vs baseline: 1.2248x; 1.2248x over previous
#include <cuda_runtime.h>
#include <cuda_fp16.h>
#include <cstdint>

// Problem constants
#define BB 16
#define SS 4096
#define EE 1024
#define HH 512
#define NROWS (BB*SS)          // 65536
#define NSPLIT 8               // H split (BN=64)
#define CSPLIT 32              // s-split for context pass

// GEMM tiling: BM=128 x BN=64, 128 threads (4 warps, warp tile 64x32)
#define BM 128
#define BN 64
#define BK 64                  // fp16 elems = 128B rows (SW128 atom)
#define KITERS (EE/BK)         // 16
#define STAGES 2
#define A_BYTES (BM*BK*2)      // 16384
#define B_BYTES (BN*BK*2)      // 8192
#define STAGE_BYTES (A_BYTES + B_BYTES)  // 24576

// Persistent GEMM scheduling (no inter-CTA deps; residency not required)
#define NCTA 592               // 148 SMs x 4 CTAs
#define NTILE (NROWS/BM)       // 512 m-tiles
#define LOOK (NCTA/8)          // 74 tile groups

// Scratch (__device__ globals; allocation-free rule), 16B+ aligned.
__device__ __align__(128) __half g_encH[(size_t)NROWS*EE];   // fp16 encoder copy
__device__ __align__(128) __half g_WeTh[HH*EE];              // We^T fp16, K-major
__device__ __align__(128) float  g_comb[BB*HH];              // dec_proj + bd + be
__device__ __align__(128) float  g_partial[NSPLIT*NROWS];    // partial scores
__device__ __align__(128) float  g_attn[NROWS];              // softmax weights
__device__ __align__(128) float  g_ctx_part[CSPLIT*BB*EE];   // context partials

__device__ __forceinline__ uint32_t smem_u32(const void* p) {
    uint32_t a;
    asm("{ .reg .u64 t; cvta.to.shared.u64 t, %1; cvt.u32.u64 %0, t; }" : "=r"(a) : "l"(p));
    return a;
}
__device__ __forceinline__ void cp16(uint32_t dst, const void* src) {
    asm volatile("cp.async.cg.shared.global [%0], [%1], 16;" :: "r"(dst), "l"(src) : "memory");
}
__device__ __forceinline__ void ldmatrix_x4(uint32_t r[4], uint32_t addr) {
    asm volatile("ldmatrix.sync.aligned.m8n8.x4.shared.b16 {%0,%1,%2,%3}, [%4];"
                 : "=r"(r[0]), "=r"(r[1]), "=r"(r[2]), "=r"(r[3]) : "r"(addr));
}
__device__ __forceinline__ void mma_f16(float d[4], const uint32_t a[4], const uint32_t b[2]) {
    asm volatile(
        "mma.sync.aligned.m16n8k16.row.col.f32.f16.f16.f32 "
        "{%0,%1,%2,%3}, {%4,%5,%6,%7}, {%8,%9}, {%0,%1,%2,%3};"
        : "+f"(d[0]), "+f"(d[1]), "+f"(d[2]), "+f"(d[3])
        : "r"(a[0]), "r"(a[1]), "r"(a[2]), "r"(a[3]), "r"(b[0]), "r"(b[1]));
}

// ---------------------------------------------------------------------------
// Convert encoder fp32 -> fp16. 32 floats per thread (8 staged float4 loads).
// ---------------------------------------------------------------------------
__global__ __launch_bounds__(256) void convert_enc_kernel(const float4* __restrict__ in) {
    const size_t i = (size_t)blockIdx.x * 256 + threadIdx.x;
    float4 v[8];
    #pragma unroll
    for (int j = 0; j < 8; j++) v[j] = in[i*8 + j];
    #pragma unroll
    for (int j = 0; j < 4; j++) {
        __half2 h0 = __floats2half2_rn(v[2*j].x,   v[2*j].y);
        __half2 h1 = __floats2half2_rn(v[2*j].z,   v[2*j].w);
        __half2 h2 = __floats2half2_rn(v[2*j+1].x, v[2*j+1].y);
        __half2 h3 = __floats2half2_rn(v[2*j+1].z, v[2*j+1].w);
        uint4 o;
        o.x = *reinterpret_cast<uint32_t*>(&h0);
        o.y = *reinterpret_cast<uint32_t*>(&h1);
        o.z = *reinterpret_cast<uint32_t*>(&h2);
        o.w = *reinterpret_cast<uint32_t*>(&h3);
        reinterpret_cast<uint4*>(g_encH)[i*4 + j] = o;
    }
}

// ---------------------------------------------------------------------------
// We [1024,512] -> g_WeTh [512,1024] fp16 (transposed, K-major).
// ---------------------------------------------------------------------------
__global__ __launch_bounds__(256) void convert_we_kernel(const float* __restrict__ We) {
    __shared__ float t[32][33];
    const int bx = blockIdx.x;  // K block (32)
    const int by = blockIdx.y;  // N block (16)
    const int x = threadIdx.x & 31;
    const int y = threadIdx.x >> 5;
    #pragma unroll
    for (int i = 0; i < 32; i += 8)
        t[y + i][x] = We[(bx*32 + y + i)*HH + by*32 + x];
    __syncthreads();
    #pragma unroll
    for (int i = 0; i < 32; i += 8)
        g_WeTh[(by*32 + y + i)*EE + bx*32 + x] = __float2half_rn(t[x][y + i]);
}

// ---------------------------------------------------------------------------
// dec_proj: comb[b,h] = dec[b,:] @ Wd[:,h] + bd[h] + be[h].
// Grid (16, 8): 64 h-lanes x 4 K-quarters; smem combine.
// ---------------------------------------------------------------------------
__global__ __launch_bounds__(256) void dec_proj_kernel(
    const float* __restrict__ dec, const float* __restrict__ Wd,
    const float* __restrict__ be, const float* __restrict__ bd) {
    __shared__ float sd[EE];
    __shared__ float part[4][64];
    const int b = blockIdx.x;
    const int hl = threadIdx.x & 63;
    const int q  = threadIdx.x >> 6;          // 0..3
    const int h  = blockIdx.y * 64 + hl;
    for (int i = threadIdx.x; i < EE; i += 256) sd[i] = dec[b*EE + i];
    __syncthreads();
    const float* wp = Wd + (size_t)(q*256)*HH + h;
    const float* dp = sd + q*256;
    float a0 = 0.f, a1 = 0.f, a2 = 0.f, a3 = 0.f;
    #pragma unroll 4
    for (int k = 0; k < 256; k += 4) {
        a0 += dp[k  ] * wp[(size_t)(k  )*HH];
        a1 += dp[k+1] * wp[(size_t)(k+1)*HH];
        a2 += dp[k+2] * wp[(size_t)(k+2)*HH];
        a3 += dp[k+3] * wp[(size_t)(k+3)*HH];
    }
    part[q][hl] = (a0 + a1) + (a2 + a3);
    __syncthreads();
    if (q == 0)
        g_comb[b*HH + h] = (part[0][hl] + part[1][hl]) + (part[2][hl] + part[3][hl])
                         + bd[h] + be[h];
}

// ---------------------------------------------------------------------------
// PERSISTENT fp16 GEMM (mma.m16n8k16) + tanh score epilogue.
// Grid = 592 CTAs. CTA c: n = c&7 fixed; m-tiles (c>>3) + 74k.
// Per tile: R14's 2-stage cp.async ring + single-buffered fragments.
// No inter-CTA dependencies (safe regardless of residency).
// ---------------------------------------------------------------------------
__global__ __launch_bounds__(128, 4) void gemm_score_f16(const float* __restrict__ Wo) {
    extern __shared__ char dsmem_raw[];
    __shared__ float red[2][BM];
    __shared__ float sm_comb[BN], sm_wo[BN];

    const int tid = threadIdx.x;
    const int c   = blockIdx.x;
    const int n   = c & 7;
    const int n0  = n * BN;
    const int cg  = c >> 3;

    const uint32_t smem_base = (smem_u32(dsmem_raw) + 127u) & ~127u;

    if (tid < BN) sm_wo[tid] = Wo[n0 + tid];

    const int warp = tid >> 5;
    const int lane = tid & 31;
    const int wm = warp >> 1;       // m-warp: rows wm*64..+63
    const int wn = warp & 1;        // n-warp: cols wn*32..+31
    const int g  = lane >> 2;
    const int tig = lane & 3;

    const __half* gB = g_WeTh + (size_t)n0 * EE;

    const int lrow = tid >> 3;          // 0..15
    const int lcb  = (tid & 7) * 16;
    const uint32_t st_sw = (uint32_t)(lrow*128 + lcb) ^ ((lrow & 7) << 4);

    uint32_t a_raw[4], a_xor[4];
    #pragma unroll
    for (int mb = 0; mb < 4; mb++) {
        int row = wm*64 + mb*16 + (lane & 15);
        a_raw[mb] = row*128 + ((lane >> 4) * 16);
        a_xor[mb] = (row & 7) << 4;
    }
    uint32_t b_raw[2], b_xor[2];
    #pragma unroll
    for (int p = 0; p < 2; p++) {
        int row = wn*32 + p*16 + ((lane & 16) ? 8 : 0) + (lane & 7);
        b_raw[p] = row*128 + (((lane >> 3) & 1) * 16);
        b_xor[p] = (row & 7) << 4;
    }

    for (int m = cg; m < NTILE; m += LOOK) {
        const int r0 = m * BM;
        const int b  = r0 >> 12;
        if (tid < BN) sm_comb[tid] = g_comb[b*HH + n0 + tid];
        const __half* gA = g_encH + (size_t)r0 * EE;

        float acc[4][4][4];
        #pragma unroll
        for (int mb = 0; mb < 4; mb++)
            #pragma unroll
            for (int nb = 0; nb < 4; nb++)
                #pragma unroll
                for (int e = 0; e < 4; e++) acc[mb][nb][e] = 0.f;

        // prologue: fill stages 0,1
        #pragma unroll
        for (int p = 0; p < STAGES; p++) {
            uint32_t stA = smem_base + p*STAGE_BYTES;
            uint32_t stB = stA + A_BYTES;
            const int k0 = p * BK;
            #pragma unroll
            for (int u = 0; u < 8; u++)
                cp16(stA + st_sw + u*2048, (const char*)(gA + (size_t)(lrow + u*16)*EE + k0) + lcb);
            #pragma unroll
            for (int u = 0; u < 4; u++)
                cp16(stB + st_sw + u*2048, (const char*)(gB + (size_t)(lrow + u*16)*EE + k0) + lcb);
            asm volatile("cp.async.commit_group;" ::: "memory");
        }

        for (int i = 0; i < KITERS; i++) {
            asm volatile("cp.async.wait_group 1;" ::: "memory");
            __syncthreads();

            const uint32_t stA = smem_base + (i & 1)*STAGE_BYTES;
            const uint32_t stB = stA + A_BYTES;

            #pragma unroll
            for (int ks = 0; ks < 4; ks++) {
                uint32_t afr[4][4], bfr[4][2];
                #pragma unroll
                for (int mb = 0; mb < 4; mb++)
                    ldmatrix_x4(afr[mb], stA + ((a_raw[mb] + ks*32) ^ a_xor[mb]));
                #pragma unroll
                for (int p = 0; p < 2; p++) {
                    uint32_t r[4];
                    ldmatrix_x4(r, stB + ((b_raw[p] + ks*32) ^ b_xor[p]));
                    bfr[2*p][0]   = r[0]; bfr[2*p][1]   = r[1];
                    bfr[2*p+1][0] = r[2]; bfr[2*p+1][1] = r[3];
                }
                #pragma unroll
                for (int mb = 0; mb < 4; mb++)
                    #pragma unroll
                    for (int nb = 0; nb < 4; nb++)
                        mma_f16(acc[mb][nb], afr[mb], bfr[nb]);
            }

            __syncthreads();
            if (i + 2 < KITERS) {
                uint32_t nA = smem_base + (i & 1)*STAGE_BYTES;
                uint32_t nB = nA + A_BYTES;
                const int k0 = (i + 2) * BK;
                #pragma unroll
                for (int u = 0; u < 8; u++)
                    cp16(nA + st_sw + u*2048, (const char*)(gA + (size_t)(lrow + u*16)*EE + k0) + lcb);
                #pragma unroll
                for (int u = 0; u < 4; u++)
                    cp16(nB + st_sw + u*2048, (const char*)(gB + (size_t)(lrow + u*16)*EE + k0) + lcb);
            }
            asm volatile("cp.async.commit_group;" ::: "memory");
        }
        asm volatile("cp.async.wait_group 0;" ::: "memory");

        // Epilogue: score = sum_n tanh(acc + comb[n]) * wo[n]
        float rs[4][2];
        #pragma unroll
        for (int mb = 0; mb < 4; mb++) { rs[mb][0] = 0.f; rs[mb][1] = 0.f; }
        #pragma unroll
        for (int mb = 0; mb < 4; mb++) {
            #pragma unroll
            for (int nb = 0; nb < 4; nb++) {
                int col = wn*32 + nb*8 + tig*2;
                float c0 = sm_comb[col], c1 = sm_comb[col+1];
                float w0 = sm_wo[col],   w1 = sm_wo[col+1];
                float t0, t1, t2, t3;
                asm("tanh.approx.f32 %0, %1;" : "=f"(t0) : "f"(acc[mb][nb][0] + c0));
                asm("tanh.approx.f32 %0, %1;" : "=f"(t1) : "f"(acc[mb][nb][1] + c1));
                asm("tanh.approx.f32 %0, %1;" : "=f"(t2) : "f"(acc[mb][nb][2] + c0));
                asm("tanh.approx.f32 %0, %1;" : "=f"(t3) : "f"(acc[mb][nb][3] + c1));
                rs[mb][0] += t0*w0 + t1*w1;
                rs[mb][1] += t2*w0 + t3*w1;
            }
        }
        #pragma unroll
        for (int mb = 0; mb < 4; mb++)
            #pragma unroll
            for (int hh = 0; hh < 2; hh++) {
                float v = rs[mb][hh];
                v += __shfl_xor_sync(0xffffffffu, v, 1);
                v += __shfl_xor_sync(0xffffffffu, v, 2);
                if (tig == 0) red[wn][wm*64 + mb*16 + hh*8 + g] = v;
            }
        __syncthreads();
        if (tid < BM)
            g_partial[n * NROWS + r0 + tid] = red[0][tid] + red[1][tid];
        __syncthreads();   // drain red/sm_comb reads before next item reuses them
    }
}

// ---------------------------------------------------------------------------
// softmax over S per batch (sums 8 N-chunk partials)
// ---------------------------------------------------------------------------
__global__ __launch_bounds__(1024) void softmax_kernel() {
    const int b = blockIdx.x;
    const int tid = threadIdx.x;
    __shared__ float sred[32];
    __shared__ float sbcast;

    float sc[4];
    float m = -1e30f;
    #pragma unroll
    for (int i = 0; i < 4; i++) {
        int s = b*SS + tid + i*1024;
        float v = 0.f;
        #pragma unroll
        for (int p = 0; p < NSPLIT; p++) v += g_partial[p*NROWS + s];
        sc[i] = v;
        m = fmaxf(m, v);
    }
    #pragma unroll
    for (int o = 16; o; o >>= 1) m = fmaxf(m, __shfl_xor_sync(0xffffffffu, m, o));
    if ((tid & 31) == 0) sred[tid >> 5] = m;
    __syncthreads();
    if (tid < 32) {
        float v = sred[tid];
        #pragma unroll
        for (int o = 16; o; o >>= 1) v = fmaxf(v, __shfl_xor_sync(0xffffffffu, v, o));
        if (tid == 0) sbcast = v;
    }
    __syncthreads();
    const float bm = sbcast;

    float sum = 0.f;
    #pragma unroll
    for (int i = 0; i < 4; i++) { sc[i] = __expf(sc[i] - bm); sum += sc[i]; }
    #pragma unroll
    for (int o = 16; o; o >>= 1) sum += __shfl_xor_sync(0xffffffffu, sum, o);
    __syncthreads();
    if ((tid & 31) == 0) sred[tid >> 5] = sum;
    __syncthreads();
    if (tid < 32) {
        float v = sred[tid];
        #pragma unroll
        for (int o = 16; o; o >>= 1) v += __shfl_xor_sync(0xffffffffu, v, o);
        if (tid == 0) sbcast = v;
    }
    __syncthreads();
    const float inv = 1.0f / sbcast;
    #pragma unroll
    for (int i = 0; i < 4; i++) g_attn[b*SS + tid + i*1024] = sc[i] * inv;
}

// ---------------------------------------------------------------------------
// Context partials from fp16 encoder copy. Grid (16, 32), block 256.
// ---------------------------------------------------------------------------
__global__ __launch_bounds__(256) void ctx_partial_kernel() {
    __shared__ float sa[128];
    __shared__ float part[128][8];
    const int b = blockIdx.x, sp = blockIdx.y;
    const int tid = threadIdx.x;
    const int half = tid >> 7;
    const int c = tid & 127;
    if (tid < 128) sa[tid] = g_attn[b*SS + sp*128 + tid];
    __syncthreads();

    const __half* ep = g_encH + ((size_t)(b*SS + sp*128 + half)) * EE + c*8;
    float a[8] = {0,0,0,0,0,0,0,0};
    #pragma unroll 8
    for (int s = 0; s < 128; s += 2) {
        uint4 v = *reinterpret_cast<const uint4*>(ep + (size_t)s*EE);
        float w = sa[s + half];
        __half2 h0 = *reinterpret_cast<__half2*>(&v.x);
        __half2 h1 = *reinterpret_cast<__half2*>(&v.y);
        __half2 h2 = *reinterpret_cast<__half2*>(&v.z);
        __half2 h3 = *reinterpret_cast<__half2*>(&v.w);
        float2 f0 = __half22float2(h0), f1 = __half22float2(h1);
        float2 f2 = __half22float2(h2), f3 = __half22float2(h3);
        a[0] += w*f0.x; a[1] += w*f0.y; a[2] += w*f1.x; a[3] += w*f1.y;
        a[4] += w*f2.x; a[5] += w*f2.y; a[6] += w*f3.x; a[7] += w*f3.y;
    }
    if (half == 1) {
        #pragma unroll
        for (int j = 0; j < 8; j++) part[c][j] = a[j];
    }
    __syncthreads();
    if (half == 0) {
        float4 o0, o1;
        o0.x = a[0] + part[c][0]; o0.y = a[1] + part[c][1];
        o0.z = a[2] + part[c][2]; o0.w = a[3] + part[c][3];
        o1.x = a[4] + part[c][4]; o1.y = a[5] + part[c][5];
        o1.z = a[6] + part[c][6]; o1.w = a[7] + part[c][7];
        float* dst = &g_ctx_part[(size_t)(sp*BB + b)*EE + c*8];
        *reinterpret_cast<float4*>(dst)     = o0;
        *reinterpret_cast<float4*>(dst + 4) = o1;
    }
}

// ---------------------------------------------------------------------------
// Final reduce of context partials.
// ---------------------------------------------------------------------------
__global__ __launch_bounds__(256) void ctx_reduce_kernel(float* __restrict__ out) {
    const int i = blockIdx.x * 256 + threadIdx.x;  // 16384 outputs
    float acc = 0.f;
    #pragma unroll
    for (int s = 0; s < CSPLIT; s++) acc += g_ctx_part[(size_t)s*BB*EE + i];
    out[i] = acc;
}

// ---------------------------------------------------------------------------
extern "C" void kernel_launch(void* const* d_in, const int* in_sizes, int n_in,
                              void* d_out, int out_size) {
    const float* enc = (const float*)d_in[0];  // [16,4096,1024]
    const float* dec = (const float*)d_in[1];  // [16,1024]
    const float* We  = (const float*)d_in[2];  // [1024,512]
    const float* be  = (const float*)d_in[3];  // [512]
    const float* Wd  = (const float*)d_in[4];  // [1024,512]
    const float* bd  = (const float*)d_in[5];  // [512]
    const float* Wo  = (const float*)d_in[6];  // [512,1]
    // d_in[7] = bo: softmax shift-invariant -> unused.

    // One-time side stream + events (resource init; captured graph identical
    // on every capture).
    static cudaStream_t s2 = nullptr;
    static cudaEvent_t ev_fork = nullptr, ev_join = nullptr;
    if (s2 == nullptr) {
        cudaStreamCreateWithFlags(&s2, cudaStreamNonBlocking);
        cudaEventCreateWithFlags(&ev_fork, cudaEventDisableTiming);
        cudaEventCreateWithFlags(&ev_join, cudaEventDisableTiming);
    }

    const int dyn_smem = STAGES*STAGE_BYTES + 256;  // 49408
    cudaFuncSetAttribute(gemm_score_f16,
                         cudaFuncAttributeMaxDynamicSharedMemorySize, dyn_smem);

    // Fork: small weight-side kernels on s2, overlapping convert_enc.
    cudaEventRecord(ev_fork, 0);
    cudaStreamWaitEvent(s2, ev_fork, 0);
    convert_we_kernel<<<dim3(EE/32, HH/32), 256, 0, s2>>>(We);
    dec_proj_kernel<<<dim3(BB, HH/64), 256, 0, s2>>>(dec, Wd, be, bd);
    cudaEventRecord(ev_join, s2);

    // Main chain on the default stream.
    convert_enc_kernel<<<(NROWS*(EE/32))/256, 256>>>((const float4*)enc);
    cudaStreamWaitEvent(0, ev_join, 0);
    gemm_score_f16<<<NCTA, 128, dyn_smem>>>(Wo);
    softmax_kernel<<<BB, 1024>>>();
    ctx_partial_kernel<<<dim3(BB, CSPLIT), 256>>>();
    ctx_reduce_kernel<<<BB*EE/256, 256>>>((float*)d_out);
}